// round 11
// baseline (speedup 1.0000x reference)
#include <cuda_runtime.h>
#include <cuda_bf16.h>

// Shapes (fixed by the problem)
#define B_  2
#define T_  512
#define N_  512
#define H_  64
#define S_  8
#define C_  8

// Edge-kernel tiling: block = 256 edges (32 i x 8 j), N=64 k, K=64 per array
#define TIB 32
#define TJB 8

// ---------------------------------------------------------------------------
// fp16 mma helpers
// ---------------------------------------------------------------------------
__device__ __forceinline__ unsigned pack_f16x2(float lo, float hi) {
    unsigned r;
    asm("cvt.rn.f16x2.f32 %0, %1, %2;" : "=r"(r) : "f"(hi), "f"(lo));
    return r;
}
__device__ __forceinline__ void mma_f16(float* c, const unsigned* a, const unsigned* b) {
    asm("mma.sync.aligned.m16n8k16.row.col.f32.f16.f16.f32 "
        "{%0,%1,%2,%3}, {%4,%5,%6,%7}, {%8,%9}, {%0,%1,%2,%3};"
        : "+f"(c[0]), "+f"(c[1]), "+f"(c[2]), "+f"(c[3])
        : "r"(a[0]), "r"(a[1]), "r"(a[2]), "r"(a[3]), "r"(b[0]), "r"(b[1]));
}

// ---------------------------------------------------------------------------
// Device scratch (no allocations allowed)
// ---------------------------------------------------------------------------
__device__ float g_repr[B_ * N_ * H_];   // node_repr
__device__ float g_Ai  [B_ * N_ * H_];   // repr @ W3[0:64]   + b3
__device__ float g_Bj  [B_ * N_ * H_];   // repr @ W3[64:128]
__device__ float g_deg [B_ * N_];        // degree accumulators
// per-node reduction stats
__device__ float g_s_sum[B_ * N_];
__device__ float g_s_sq [B_ * N_];
__device__ float g_s_cnt[B_ * N_];
__device__ float g_s_ms [B_ * N_];
__device__ int   g_s_last[B_ * N_];
// W3c/W3d pre-converted to f16x2 B-fragments for m16n8k16.row.col, interleaved:
// [ks][nt][lane][4 words: bC0 bC1 bD0 bD1] -> one LDS.128 per (ks,nt)
__device__ unsigned g_Wf[4 * 8 * 32 * 4];    // 16KB

// ---------------------------------------------------------------------------
// K0: init — zero accumulators (blocks 0..3) + fragment prep (blocks 4..19).
// m16n8k16.row.col B-frag: b0 = {k=2t,2t+1 | n=g}, b1 = {k=2t+8,2t+9 | n=g}.
// ---------------------------------------------------------------------------
__global__ void k_init(const float* __restrict__ W3) {
    if (blockIdx.x < 4) {
        int t = blockIdx.x * 256 + threadIdx.x;    // 0..1023
        g_deg[t] = 0.0f;
        g_s_sum[t] = 0.0f; g_s_sq[t] = 0.0f;
        g_s_cnt[t] = 0.0f; g_s_ms[t] = 0.0f;
        g_s_last[t] = 0;
    } else {
        int f = (blockIdx.x - 4) * 256 + threadIdx.x;  // 0..4095
        int w    = f & 3;            // 0=bC0 1=bC1 2=bD0 3=bD1
        int lane = (f >> 2) & 31;
        int nt   = (f >> 7) & 7;
        int ks   = (f >> 10) & 3;
        int t = lane & 3, g = lane >> 2;
        int arr = w >> 1;            // 0 = abs-part (W3 rows 128+), 1 = prod (192+)
        int k   = ks * 16 + 2 * t + (w & 1) * 8;   // within [0,64)
        int n   = nt * 8 + g;
        int rb  = 128 + arr * 64;
        g_Wf[f] = pack_f16x2(W3[(rb + k) * 64 + n], W3[(rb + k + 1) * 64 + n]);
    }
}

// ---------------------------------------------------------------------------
// K1a: chip-wide T-chunked reduction. grid (N/32, B, 8), block (32, 8).
// ---------------------------------------------------------------------------
__global__ void k_reduce(const float* __restrict__ x,
                         const float* __restrict__ mask) {
    const int tx = threadIdx.x, ty = threadIdx.y;
    const int b  = blockIdx.y;
    const int n  = blockIdx.x * 32 + tx;
    const int t0 = blockIdx.z * 64;

    __shared__ float s_sum[8][33], s_sq[8][33], s_cnt[8][33], s_ms[8][33];
    __shared__ int   s_last[8][33];

    const float* xb = x    + (size_t)b * T_ * N_;
    const float* mb = mask + (size_t)b * T_ * N_;

    float sum = 0.f, sq = 0.f, cnt = 0.f, ms = 0.f;
    int   lastt = -1;
    #pragma unroll
    for (int it = 0; it < 8; it++) {
        int t = t0 + ty + it * 8;
        float xv = xb[t * N_ + n];
        float mv = mb[t * N_ + n];
        float ob = 1.0f - mv;
        sum += xv * ob;
        sq  += xv * xv * ob;
        cnt += ob;
        ms  += mv;
        if (ob > 0.5f) lastt = t;
    }
    s_sum[ty][tx] = sum; s_sq[ty][tx] = sq; s_cnt[ty][tx] = cnt;
    s_ms[ty][tx] = ms;   s_last[ty][tx] = lastt;
    __syncthreads();

    if (ty == 0) {
        for (int r = 1; r < 8; r++) {
            sum += s_sum[r][tx]; sq += s_sq[r][tx]; cnt += s_cnt[r][tx];
            ms  += s_ms[r][tx];
            lastt = max(lastt, s_last[r][tx]);
        }
        int idx = b * N_ + n;
        atomicAdd(&g_s_sum[idx], sum);
        atomicAdd(&g_s_sq [idx], sq);
        atomicAdd(&g_s_cnt[idx], cnt);
        atomicAdd(&g_s_ms [idx], ms);
        if (lastt >= 0) atomicMax(&g_s_last[idx], lastt);
    }
}

// ---------------------------------------------------------------------------
// K1b (fused): finalize stats -> feats -> layer1 -> layer2 -> Ai/Bj.
// grid 64 blocks x 16 nodes; block 256 = 16 nodes x 16 k-lanes (4 k each).
// ---------------------------------------------------------------------------
__global__ __launch_bounds__(256)
void k_node(const float* __restrict__ x,
            const float* __restrict__ statc,
            const float* __restrict__ W1,
            const float* __restrict__ b1,
            const float* __restrict__ W2,
            const float* __restrict__ b2,
            const float* __restrict__ W3,
            const float* __restrict__ b3) {
    __shared__ float s_w[128 * 64];      // 32KB union: [W1(768) W2(4096)] then W3ab(8192)
    __shared__ float s_f[16][13];        // feats
    __shared__ float s_h[16][65];        // hidden
    __shared__ float s_r[16][65];        // repr

    const int tid = threadIdx.x;
    const int ng0 = blockIdx.x * 16;     // flat (b*N + n) base; never straddles batch

    for (int idx = tid; idx < 768; idx += 256)  s_w[idx] = W1[idx];
    for (int idx = tid; idx < 4096; idx += 256) s_w[768 + idx] = W2[idx];

    if (tid < 16) {
        int idx = ng0 + tid;
        int b = idx >> 9, n = idx & (N_ - 1);
        float sum = g_s_sum[idx], sq = g_s_sq[idx];
        float cnt = g_s_cnt[idx], ms = g_s_ms[idx];
        int lastt = g_s_last[idx];
        float count = fmaxf(cnt, 1.0f);
        float mean  = sum / count;
        float var   = (sq - 2.0f * mean * sum + mean * mean * cnt) / count;
        float stdv  = sqrtf(fmaxf(var, 0.0f) + 1e-6f);
        float last  = x[((size_t)b * T_ + lastt) * N_ + n];
        s_f[tid][0] = mean; s_f[tid][1] = stdv; s_f[tid][2] = last;
        s_f[tid][3] = ms * (1.0f / (float)T_);
    }
    if (tid < 128) {
        int nl = tid >> 3, s = tid & 7;
        s_f[nl][4 + s] = statc[((ng0 + nl) & (N_ - 1)) * S_ + s];
    }
    __syncthreads();

    const int nl = tid >> 4;             // node-in-block
    const int kl = tid & 15;             // k-lane

    #pragma unroll
    for (int kk = 0; kk < 4; kk++) {
        int k = kl + 16 * kk;
        float a = b1[k];
        #pragma unroll
        for (int f = 0; f < 12; f++) a += s_f[nl][f] * s_w[f * 64 + k];
        s_h[nl][k] = fmaxf(a, 0.0f);
    }
    __syncthreads();

    #pragma unroll
    for (int kk = 0; kk < 4; kk++) {
        int k = kl + 16 * kk;
        float a = b2[k];
        #pragma unroll
        for (int h = 0; h < 64; h++) a += s_h[nl][h] * s_w[768 + h * 64 + k];
        float r = fmaxf(a, 0.0f);
        s_r[nl][k] = r;
        g_repr[(ng0 + nl) * H_ + k] = r;
    }
    __syncthreads();

    for (int idx = tid; idx < 8192; idx += 256) s_w[idx] = W3[idx];
    __syncthreads();

    #pragma unroll
    for (int kk = 0; kk < 4; kk++) {
        int k = kl + 16 * kk;
        float a = b3[k], bj = 0.0f;
        #pragma unroll
        for (int h = 0; h < 64; h++) {
            float r = s_r[nl][h];
            a  += r * s_w[h * 64 + k];
            bj += r * s_w[(64 + h) * 64 + k];
        }
        g_Ai[(ng0 + nl) * H_ + k] = a;
        g_Bj[(ng0 + nl) * H_ + k] = bj;
    }
}

// ---------------------------------------------------------------------------
// K4: edge MLP via fp16 mma.sync m16n8k16 (fp32 accum); prior inline.
// Block tile: M=256 edges (32i x 8j), per-array K=64 -> 4 k16 steps.
// 8 warps = 8 m-groups (32 edges), each covers full N=64.
// A fragments built in regs from hi/hj (float2 LDS + cvt.rn.f16x2 pack, RNE);
// B fragments pre-interleaved so one LDS.128 fetches both (abs, prod) vectors.
// grid (N/TJB, N/TIB, B), block 256.
// ---------------------------------------------------------------------------
__global__ __launch_bounds__(256)
void k_edge(const float* __restrict__ W4,
            const float* __restrict__ b4p,
            const float* __restrict__ coords,
            float* __restrict__ out) {
    __shared__ float s_hi[32][68];               // pad 68: conflict-free A builds
    __shared__ float s_hj[8][68];
    __shared__ unsigned s_Wf[4][8][32][4];       // 16KB frag buffer, reused as Ai/Bj
    __shared__ float s_ed[256];                  // per-edge pre-b4 sums
    __shared__ float s_ad[256];
    __shared__ float s_W4[64];
    __shared__ float s_ci[32][8];
    __shared__ float s_cj[8][8];

    const int tid = threadIdx.x;
    const int b   = blockIdx.z;
    const int i0  = blockIdx.y * TIB;
    const int j0  = blockIdx.x * TJB;
    const int bN  = b * N_;

    const float* reprB = g_repr + (size_t)bN * H_;

    // prologue
    for (int idx = tid; idx < 32 * 64; idx += 256)
        s_hi[idx >> 6][idx & 63] = reprB[(i0 + (idx >> 6)) * H_ + (idx & 63)];
    for (int idx = tid; idx < 8 * 64; idx += 256)
        s_hj[idx >> 6][idx & 63] = reprB[(j0 + (idx >> 6)) * H_ + (idx & 63)];
    {
        const uint4* src = (const uint4*)g_Wf;
        uint4* dst = (uint4*)&s_Wf[0][0][0][0];
        for (int idx = tid; idx < 1024; idx += 256) dst[idx] = src[idx];
    }
    if (tid < 64) s_W4[tid] = W4[tid];
    s_ci[tid >> 3][tid & 7] = coords[(i0 + (tid >> 3)) * C_ + (tid & 7)];
    if (tid < 64) s_cj[tid >> 3][tid & 7] = coords[(j0 + (tid >> 3)) * C_ + (tid & 7)];
    __syncthreads();

    const int wid = tid >> 5, lane = tid & 31;   // warp = m-group of 32 edges
    const int g = lane >> 2, t = lane & 3;       // g = jl, t = k-quad

    float acc[2][8][4];
    #pragma unroll
    for (int mt = 0; mt < 2; mt++)
        #pragma unroll
        for (int nt = 0; nt < 8; nt++)
            #pragma unroll
            for (int q = 0; q < 4; q++) acc[mt][nt][q] = 0.0f;

    #pragma unroll
    for (int ks = 0; ks < 4; ks++) {             // k16 step over H=64
        const int hb = ks * 16 + 2 * t;
        const float2 hjA = *(const float2*)&s_hj[g][hb];
        const float2 hjB = *(const float2*)&s_hj[g][hb + 8];
        unsigned aD[2][4], aP[2][4];
        #pragma unroll
        for (int mt = 0; mt < 2; mt++) {
            const int il0 = wid * 4 + mt * 2;
            const float2 x0  = *(const float2*)&s_hi[il0][hb];
            const float2 x0b = *(const float2*)&s_hi[il0][hb + 8];
            const float2 x1  = *(const float2*)&s_hi[il0 + 1][hb];
            const float2 x1b = *(const float2*)&s_hi[il0 + 1][hb + 8];
            aD[mt][0] = pack_f16x2(fabsf(x0.x  - hjA.x), fabsf(x0.y  - hjA.y));
            aD[mt][1] = pack_f16x2(fabsf(x1.x  - hjA.x), fabsf(x1.y  - hjA.y));
            aD[mt][2] = pack_f16x2(fabsf(x0b.x - hjB.x), fabsf(x0b.y - hjB.y));
            aD[mt][3] = pack_f16x2(fabsf(x1b.x - hjB.x), fabsf(x1b.y - hjB.y));
            aP[mt][0] = pack_f16x2(x0.x  * hjA.x, x0.y  * hjA.y);
            aP[mt][1] = pack_f16x2(x1.x  * hjA.x, x1.y  * hjA.y);
            aP[mt][2] = pack_f16x2(x0b.x * hjB.x, x0b.y * hjB.y);
            aP[mt][3] = pack_f16x2(x1b.x * hjB.x, x1b.y * hjB.y);
        }
        #pragma unroll
        for (int nt = 0; nt < 8; nt++) {
            uint4 fr = *(const uint4*)&s_Wf[ks][nt][lane][0];
            unsigned bC[2] = { fr.x, fr.y };
            unsigned bD[2] = { fr.z, fr.w };
            #pragma unroll
            for (int mt = 0; mt < 2; mt++) {
                mma_f16(acc[mt][nt], aD[mt], bC);
                mma_f16(acc[mt][nt], aP[mt], bD);
            }
        }
    }

    // restage Ai/Bj into smem reused from the fragment buffer (16KB >= 10KB)
    __syncthreads();
    float* s_Ais = (float*)&s_Wf[0][0][0][0];    // [32][64]
    float* s_Bjs = s_Ais + 32 * 64;              // [8][64]
    {
        const float4* srcA = (const float4*)(g_Ai + (size_t)(bN + i0) * H_);
        float4* dstA = (float4*)s_Ais;
        for (int idx = tid; idx < 512; idx += 256) dstA[idx] = srcA[idx];
        const float4* srcB = (const float4*)(g_Bj + (size_t)(bN + j0) * H_);
        float4* dstB = (float4*)s_Bjs;
        if (tid < 128) dstB[tid] = srcB[tid];
    }
    __syncthreads();

    // epilogue: e_k = relu(acc + Ai + Bj); dot with W4, quad-reduce.
    #pragma unroll
    for (int mt = 0; mt < 2; mt++) {
        #pragma unroll
        for (int half = 0; half < 2; half++) {
            const int il = wid * 4 + mt * 2 + half;
            const int jl = g;
            float s = 0.0f;
            #pragma unroll
            for (int nt = 0; nt < 8; nt++) {
                const int k0 = nt * 8 + 2 * t;
                float ab0 = s_Ais[il * 64 + k0]     + s_Bjs[jl * 64 + k0];
                float ab1 = s_Ais[il * 64 + k0 + 1] + s_Bjs[jl * 64 + k0 + 1];
                float v0 = fmaxf(acc[mt][nt][half * 2]     + ab0, 0.0f);
                float v1 = fmaxf(acc[mt][nt][half * 2 + 1] + ab1, 0.0f);
                s += v0 * s_W4[k0] + v1 * s_W4[k0 + 1];
            }
            s += __shfl_xor_sync(0xffffffffu, s, 1);
            s += __shfl_xor_sync(0xffffffffu, s, 2);
            if (t == 0) s_ed[wid * 32 + mt * 16 + half * 8 + g] = s;
        }
    }
    __syncthreads();

    {
        const float b4v = b4p[0];
        int e  = tid;                            // 0..255
        int il = e >> 3, jl = e & 7;
        int i  = i0 + il, j = j0 + jl;
        float edge = fmaxf(s_ed[e] + b4v, 0.0f);
        float d2 = 0.0f;
        #pragma unroll
        for (int c = 0; c < C_; c++) {
            float d = s_ci[il][c] - s_cj[jl][c];
            d2 += d * d;
        }
        float pr = (i == j) ? 0.0f : 1.0f / (1.0f + sqrtf(d2));
        float ad = edge * pr + ((i == j) ? 1.0f : 0.0f);
        out[((size_t)(bN + i)) * N_ + j] = ad;   // adapt (pre-normalization)
        s_ad[e] = ad;
    }
    __syncthreads();

    if (tid < 32) {
        float dsum = 0.0f;
        #pragma unroll
        for (int jl = 0; jl < 8; jl++) dsum += s_ad[tid * 8 + jl];
        atomicAdd(&g_deg[bN + i0 + tid], dsum);
    }
}

// ---------------------------------------------------------------------------
// K6: out *= inv_i * inv_j  with inline rsqrt
// ---------------------------------------------------------------------------
__global__ void k_norm(float* __restrict__ out) {
    int idx = blockIdx.x * 256 + threadIdx.x;      // one float4 each
    int j4  = (idx & 127) * 4;                     // 128 quads per row
    int bi  = idx >> 7;                            // flat b*N+i, 0..1023
    float  inv_i = rsqrtf(fmaxf(g_deg[bi], 1e-6f));
    float4 dj    = *(const float4*)&g_deg[(bi & ~(N_ - 1)) + j4];
    float4 v = ((float4*)out)[idx];
    v.x *= inv_i * rsqrtf(fmaxf(dj.x, 1e-6f));
    v.y *= inv_i * rsqrtf(fmaxf(dj.y, 1e-6f));
    v.z *= inv_i * rsqrtf(fmaxf(dj.z, 1e-6f));
    v.w *= inv_i * rsqrtf(fmaxf(dj.w, 1e-6f));
    ((float4*)out)[idx] = v;
}

// ---------------------------------------------------------------------------
// launch
// ---------------------------------------------------------------------------
extern "C" void kernel_launch(void* const* d_in, const int* in_sizes, int n_in,
                              void* d_out, int out_size) {
    const float* x      = (const float*)d_in[0];
    const float* mask   = (const float*)d_in[1];
    const float* statc  = (const float*)d_in[2];
    const float* coords = (const float*)d_in[3];
    const float* W1     = (const float*)d_in[4];
    const float* b1     = (const float*)d_in[5];
    const float* W2     = (const float*)d_in[6];
    const float* b2     = (const float*)d_in[7];
    const float* W3     = (const float*)d_in[8];
    const float* b3     = (const float*)d_in[9];
    const float* W4     = (const float*)d_in[10];
    const float* b4     = (const float*)d_in[11];
    float* out = (float*)d_out;

    k_init<<<20, 256>>>(W3);
    k_reduce<<<dim3(N_ / 32, B_, 8), dim3(32, 8)>>>(x, mask);
    k_node<<<(B_ * N_) / 16, 256>>>(x, statc, W1, b1, W2, b2, W3, b3);
    k_edge<<<dim3(N_ / TJB, N_ / TIB, B_), 256>>>(W4, b4, coords, out);
    k_norm<<<(B_ * N_ * N_ / 4) / 256, 256>>>(out);
}

// round 14
// speedup vs baseline: 1.3876x; 1.3876x over previous
#include <cuda_runtime.h>
#include <cuda_bf16.h>

// Shapes (fixed by the problem)
#define B_  2
#define T_  512
#define N_  512
#define H_  64
#define S_  8
#define C_  8

// Edge-kernel tiling: block = 256 edges (32 i x 8 j), N=64 k, K=64 per array
#define TIB 32
#define TJB 8

// ---------------------------------------------------------------------------
// fp16 mma helpers
// ---------------------------------------------------------------------------
__device__ __forceinline__ unsigned pack_f16x2(float lo, float hi) {
    unsigned r;
    asm("cvt.rn.f16x2.f32 %0, %1, %2;" : "=r"(r) : "f"(hi), "f"(lo));
    return r;
}
__device__ __forceinline__ void mma_f16(float* c, const unsigned* a, const unsigned* b) {
    asm("mma.sync.aligned.m16n8k16.row.col.f32.f16.f16.f32 "
        "{%0,%1,%2,%3}, {%4,%5,%6,%7}, {%8,%9}, {%0,%1,%2,%3};"
        : "+f"(c[0]), "+f"(c[1]), "+f"(c[2]), "+f"(c[3])
        : "r"(a[0]), "r"(a[1]), "r"(a[2]), "r"(a[3]), "r"(b[0]), "r"(b[1]));
}

// ---------------------------------------------------------------------------
// Device scratch (no allocations allowed)
// ---------------------------------------------------------------------------
__device__ float g_repr[B_ * N_ * H_];   // node_repr
__device__ float g_Ai  [B_ * N_ * H_];   // repr @ W3[0:64]   + b3
__device__ float g_Bj  [B_ * N_ * H_];   // repr @ W3[64:128]
__device__ float g_deg [B_ * N_];        // degree accumulators
// per-node reduction stats
__device__ float g_s_sum[B_ * N_];
__device__ float g_s_sq [B_ * N_];
__device__ float g_s_cnt[B_ * N_];
__device__ float g_s_ms [B_ * N_];
__device__ int   g_s_last[B_ * N_];
// W3c/W3d as f16x2 B-fragments for m16n8k16.row.col, split per array so each
// pass does one lane-contiguous LDS.64:  [ks][nt][arr][lane][2 words]
__device__ unsigned g_Wf[4 * 8 * 2 * 32 * 2];    // 16KB

// ---------------------------------------------------------------------------
// K0: init — zero accumulators (blocks 0..3) + fragment prep (blocks 4..19).
// m16n8k16.row.col B-frag: b0 = {k=2t,2t+1 | n=g}, b1 = {k=2t+8,2t+9 | n=g}.
// ---------------------------------------------------------------------------
__global__ void k_init(const float* __restrict__ W3) {
    if (blockIdx.x < 4) {
        int t = blockIdx.x * 256 + threadIdx.x;    // 0..1023
        g_deg[t] = 0.0f;
        g_s_sum[t] = 0.0f; g_s_sq[t] = 0.0f;
        g_s_cnt[t] = 0.0f; g_s_ms[t] = 0.0f;
        g_s_last[t] = 0;
    } else {
        int f = (blockIdx.x - 4) * 256 + threadIdx.x;  // 0..4095
        int p    = f & 1;            // b0 vs b1 (k offset +8)
        int lane = (f >> 1) & 31;
        int arr  = (f >> 6) & 1;     // 0 = abs-part (W3 rows 128+), 1 = prod (192+)
        int nt   = (f >> 7) & 7;
        int ks   = (f >> 10) & 3;
        int t = lane & 3, g = lane >> 2;
        int k   = ks * 16 + 2 * t + p * 8;         // within [0,64)
        int n   = nt * 8 + g;
        int rb  = 128 + arr * 64;
        g_Wf[f] = pack_f16x2(W3[(rb + k) * 64 + n], W3[(rb + k + 1) * 64 + n]);
    }
}

// ---------------------------------------------------------------------------
// K1a: chip-wide T-chunked reduction. grid (N/32, B, 8), block (32, 8).
// ---------------------------------------------------------------------------
__global__ void k_reduce(const float* __restrict__ x,
                         const float* __restrict__ mask) {
    const int tx = threadIdx.x, ty = threadIdx.y;
    const int b  = blockIdx.y;
    const int n  = blockIdx.x * 32 + tx;
    const int t0 = blockIdx.z * 64;

    __shared__ float s_sum[8][33], s_sq[8][33], s_cnt[8][33], s_ms[8][33];
    __shared__ int   s_last[8][33];

    const float* xb = x    + (size_t)b * T_ * N_;
    const float* mb = mask + (size_t)b * T_ * N_;

    float sum = 0.f, sq = 0.f, cnt = 0.f, ms = 0.f;
    int   lastt = -1;
    #pragma unroll
    for (int it = 0; it < 8; it++) {
        int t = t0 + ty + it * 8;
        float xv = xb[t * N_ + n];
        float mv = mb[t * N_ + n];
        float ob = 1.0f - mv;
        sum += xv * ob;
        sq  += xv * xv * ob;
        cnt += ob;
        ms  += mv;
        if (ob > 0.5f) lastt = t;
    }
    s_sum[ty][tx] = sum; s_sq[ty][tx] = sq; s_cnt[ty][tx] = cnt;
    s_ms[ty][tx] = ms;   s_last[ty][tx] = lastt;
    __syncthreads();

    if (ty == 0) {
        for (int r = 1; r < 8; r++) {
            sum += s_sum[r][tx]; sq += s_sq[r][tx]; cnt += s_cnt[r][tx];
            ms  += s_ms[r][tx];
            lastt = max(lastt, s_last[r][tx]);
        }
        int idx = b * N_ + n;
        atomicAdd(&g_s_sum[idx], sum);
        atomicAdd(&g_s_sq [idx], sq);
        atomicAdd(&g_s_cnt[idx], cnt);
        atomicAdd(&g_s_ms [idx], ms);
        if (lastt >= 0) atomicMax(&g_s_last[idx], lastt);
    }
}

// ---------------------------------------------------------------------------
// K1b (fused): finalize stats -> feats -> layer1 -> layer2 -> Ai/Bj.
// grid 64 blocks x 16 nodes; block 256 = 16 nodes x 16 k-lanes (4 k each).
// ---------------------------------------------------------------------------
__global__ __launch_bounds__(256)
void k_node(const float* __restrict__ x,
            const float* __restrict__ statc,
            const float* __restrict__ W1,
            const float* __restrict__ b1,
            const float* __restrict__ W2,
            const float* __restrict__ b2,
            const float* __restrict__ W3,
            const float* __restrict__ b3) {
    __shared__ float s_w[128 * 64];      // 32KB union: [W1(768) W2(4096)] then W3ab(8192)
    __shared__ float s_f[16][13];        // feats
    __shared__ float s_h[16][65];        // hidden
    __shared__ float s_r[16][65];        // repr

    const int tid = threadIdx.x;
    const int ng0 = blockIdx.x * 16;     // flat (b*N + n) base; never straddles batch

    for (int idx = tid; idx < 768; idx += 256)  s_w[idx] = W1[idx];
    for (int idx = tid; idx < 4096; idx += 256) s_w[768 + idx] = W2[idx];

    if (tid < 16) {
        int idx = ng0 + tid;
        int b = idx >> 9, n = idx & (N_ - 1);
        float sum = g_s_sum[idx], sq = g_s_sq[idx];
        float cnt = g_s_cnt[idx], ms = g_s_ms[idx];
        int lastt = g_s_last[idx];
        float count = fmaxf(cnt, 1.0f);
        float mean  = sum / count;
        float var   = (sq - 2.0f * mean * sum + mean * mean * cnt) / count;
        float stdv  = sqrtf(fmaxf(var, 0.0f) + 1e-6f);
        float last  = x[((size_t)b * T_ + lastt) * N_ + n];
        s_f[tid][0] = mean; s_f[tid][1] = stdv; s_f[tid][2] = last;
        s_f[tid][3] = ms * (1.0f / (float)T_);
    }
    if (tid < 128) {
        int nl = tid >> 3, s = tid & 7;
        s_f[nl][4 + s] = statc[((ng0 + nl) & (N_ - 1)) * S_ + s];
    }
    __syncthreads();

    const int nl = tid >> 4;             // node-in-block
    const int kl = tid & 15;             // k-lane

    #pragma unroll
    for (int kk = 0; kk < 4; kk++) {
        int k = kl + 16 * kk;
        float a = b1[k];
        #pragma unroll
        for (int f = 0; f < 12; f++) a += s_f[nl][f] * s_w[f * 64 + k];
        s_h[nl][k] = fmaxf(a, 0.0f);
    }
    __syncthreads();

    #pragma unroll
    for (int kk = 0; kk < 4; kk++) {
        int k = kl + 16 * kk;
        float a = b2[k];
        #pragma unroll
        for (int h = 0; h < 64; h++) a += s_h[nl][h] * s_w[768 + h * 64 + k];
        float r = fmaxf(a, 0.0f);
        s_r[nl][k] = r;
        g_repr[(ng0 + nl) * H_ + k] = r;
    }
    __syncthreads();

    for (int idx = tid; idx < 8192; idx += 256) s_w[idx] = W3[idx];
    __syncthreads();

    #pragma unroll
    for (int kk = 0; kk < 4; kk++) {
        int k = kl + 16 * kk;
        float a = b3[k], bj = 0.0f;
        #pragma unroll
        for (int h = 0; h < 64; h++) {
            float r = s_r[nl][h];
            a  += r * s_w[h * 64 + k];
            bj += r * s_w[(64 + h) * 64 + k];
        }
        g_Ai[(ng0 + nl) * H_ + k] = a;
        g_Bj[(ng0 + nl) * H_ + k] = bj;
    }
}

// ---------------------------------------------------------------------------
// K4: edge MLP via fp16 mma.sync m16n8k16 (fp32 accum); prior inline.
// Block tile: M=256 edges (32i x 8j), per-array K=64 -> 4 k16 steps.
// 8 warps = 8 m-groups (32 edges), each covers full N=64.
// TWO-PASS mainloop per k16-step: build aD (8 regs) -> 16 mmas -> rebuild the
// SAME regs as aP -> 16 mmas.  Halves live A-registers vs R11 (which hit 130
// regs -> 1 block/SM -> occ 12%).  __launch_bounds__(256,2) pins the target.
// grid (N/TJB, N/TIB, B), block 256.
// ---------------------------------------------------------------------------
__global__ __launch_bounds__(256, 2)
void k_edge(const float* __restrict__ W4,
            const float* __restrict__ b4p,
            const float* __restrict__ coords,
            float* __restrict__ out) {
    __shared__ float s_hi[32][68];               // pad 68: conflict-free A builds
    __shared__ float s_hj[8][68];
    __shared__ unsigned s_Wf[4][8][2][32][2];    // 16KB frag buffer, reused as Ai/Bj
    __shared__ float s_ed[256];                  // per-edge pre-b4 sums
    __shared__ float s_ad[256];
    __shared__ float s_W4[64];
    __shared__ float s_ci[32][8];
    __shared__ float s_cj[8][8];

    const int tid = threadIdx.x;
    const int b   = blockIdx.z;
    const int i0  = blockIdx.y * TIB;
    const int j0  = blockIdx.x * TJB;
    const int bN  = b * N_;

    const float* reprB = g_repr + (size_t)bN * H_;

    // prologue
    for (int idx = tid; idx < 32 * 64; idx += 256)
        s_hi[idx >> 6][idx & 63] = reprB[(i0 + (idx >> 6)) * H_ + (idx & 63)];
    for (int idx = tid; idx < 8 * 64; idx += 256)
        s_hj[idx >> 6][idx & 63] = reprB[(j0 + (idx >> 6)) * H_ + (idx & 63)];
    {
        const uint4* src = (const uint4*)g_Wf;
        uint4* dst = (uint4*)&s_Wf[0][0][0][0][0];
        for (int idx = tid; idx < 1024; idx += 256) dst[idx] = src[idx];
    }
    if (tid < 64) s_W4[tid] = W4[tid];
    s_ci[tid >> 3][tid & 7] = coords[(i0 + (tid >> 3)) * C_ + (tid & 7)];
    if (tid < 64) s_cj[tid >> 3][tid & 7] = coords[(j0 + (tid >> 3)) * C_ + (tid & 7)];
    __syncthreads();

    const int wid = tid >> 5, lane = tid & 31;   // warp = m-group of 32 edges
    const int g = lane >> 2, t = lane & 3;       // g = jl, t = k-quad

    float acc[2][8][4];
    #pragma unroll
    for (int mt = 0; mt < 2; mt++)
        #pragma unroll
        for (int nt = 0; nt < 8; nt++)
            #pragma unroll
            for (int q = 0; q < 4; q++) acc[mt][nt][q] = 0.0f;

    #pragma unroll
    for (int ks = 0; ks < 4; ks++) {             // k16 step over H=64
        const int hb = ks * 16 + 2 * t;
        const float2 hjA = *(const float2*)&s_hj[g][hb];
        const float2 hjB = *(const float2*)&s_hj[g][hb + 8];
        unsigned a[2][4];

        // ---- pass 1: |hi - hj| against W3c fragments ----
        #pragma unroll
        for (int mt = 0; mt < 2; mt++) {
            const int il0 = wid * 4 + mt * 2;
            const float2 x0  = *(const float2*)&s_hi[il0][hb];
            const float2 x0b = *(const float2*)&s_hi[il0][hb + 8];
            const float2 x1  = *(const float2*)&s_hi[il0 + 1][hb];
            const float2 x1b = *(const float2*)&s_hi[il0 + 1][hb + 8];
            a[mt][0] = pack_f16x2(fabsf(x0.x  - hjA.x), fabsf(x0.y  - hjA.y));
            a[mt][1] = pack_f16x2(fabsf(x1.x  - hjA.x), fabsf(x1.y  - hjA.y));
            a[mt][2] = pack_f16x2(fabsf(x0b.x - hjB.x), fabsf(x0b.y - hjB.y));
            a[mt][3] = pack_f16x2(fabsf(x1b.x - hjB.x), fabsf(x1b.y - hjB.y));
        }
        #pragma unroll
        for (int nt = 0; nt < 8; nt++) {
            uint2 bc = *(const uint2*)&s_Wf[ks][nt][0][lane][0];
            unsigned bB[2] = { bc.x, bc.y };
            mma_f16(acc[0][nt], a[0], bB);
            mma_f16(acc[1][nt], a[1], bB);
        }

        // ---- pass 2: hi * hj against W3d fragments (same A registers) ----
        #pragma unroll
        for (int mt = 0; mt < 2; mt++) {
            const int il0 = wid * 4 + mt * 2;
            const float2 x0  = *(const float2*)&s_hi[il0][hb];
            const float2 x0b = *(const float2*)&s_hi[il0][hb + 8];
            const float2 x1  = *(const float2*)&s_hi[il0 + 1][hb];
            const float2 x1b = *(const float2*)&s_hi[il0 + 1][hb + 8];
            a[mt][0] = pack_f16x2(x0.x  * hjA.x, x0.y  * hjA.y);
            a[mt][1] = pack_f16x2(x1.x  * hjA.x, x1.y  * hjA.y);
            a[mt][2] = pack_f16x2(x0b.x * hjB.x, x0b.y * hjB.y);
            a[mt][3] = pack_f16x2(x1b.x * hjB.x, x1b.y * hjB.y);
        }
        #pragma unroll
        for (int nt = 0; nt < 8; nt++) {
            uint2 bd = *(const uint2*)&s_Wf[ks][nt][1][lane][0];
            unsigned bB[2] = { bd.x, bd.y };
            mma_f16(acc[0][nt], a[0], bB);
            mma_f16(acc[1][nt], a[1], bB);
        }
    }

    // restage Ai/Bj into smem reused from the fragment buffer (16KB >= 10KB)
    __syncthreads();
    float* s_Ais = (float*)&s_Wf[0][0][0][0][0]; // [32][64]
    float* s_Bjs = s_Ais + 32 * 64;              // [8][64]
    {
        const float4* srcA = (const float4*)(g_Ai + (size_t)(bN + i0) * H_);
        float4* dstA = (float4*)s_Ais;
        for (int idx = tid; idx < 512; idx += 256) dstA[idx] = srcA[idx];
        const float4* srcB = (const float4*)(g_Bj + (size_t)(bN + j0) * H_);
        float4* dstB = (float4*)s_Bjs;
        if (tid < 128) dstB[tid] = srcB[tid];
    }
    __syncthreads();

    // epilogue: e_k = relu(acc + Ai + Bj); dot with W4, quad-reduce.
    #pragma unroll
    for (int mt = 0; mt < 2; mt++) {
        #pragma unroll
        for (int half = 0; half < 2; half++) {
            const int il = wid * 4 + mt * 2 + half;
            const int jl = g;
            float s = 0.0f;
            #pragma unroll
            for (int nt = 0; nt < 8; nt++) {
                const int k0 = nt * 8 + 2 * t;
                float ab0 = s_Ais[il * 64 + k0]     + s_Bjs[jl * 64 + k0];
                float ab1 = s_Ais[il * 64 + k0 + 1] + s_Bjs[jl * 64 + k0 + 1];
                float v0 = fmaxf(acc[mt][nt][half * 2]     + ab0, 0.0f);
                float v1 = fmaxf(acc[mt][nt][half * 2 + 1] + ab1, 0.0f);
                s += v0 * s_W4[k0] + v1 * s_W4[k0 + 1];
            }
            s += __shfl_xor_sync(0xffffffffu, s, 1);
            s += __shfl_xor_sync(0xffffffffu, s, 2);
            if (t == 0) s_ed[wid * 32 + mt * 16 + half * 8 + g] = s;
        }
    }
    __syncthreads();

    {
        const float b4v = b4p[0];
        int e  = tid;                            // 0..255
        int il = e >> 3, jl = e & 7;
        int i  = i0 + il, j = j0 + jl;
        float edge = fmaxf(s_ed[e] + b4v, 0.0f);
        float d2 = 0.0f;
        #pragma unroll
        for (int c = 0; c < C_; c++) {
            float d = s_ci[il][c] - s_cj[jl][c];
            d2 += d * d;
        }
        float pr = (i == j) ? 0.0f : 1.0f / (1.0f + sqrtf(d2));
        float ad = edge * pr + ((i == j) ? 1.0f : 0.0f);
        out[((size_t)(bN + i)) * N_ + j] = ad;   // adapt (pre-normalization)
        s_ad[e] = ad;
    }
    __syncthreads();

    if (tid < 32) {
        float dsum = 0.0f;
        #pragma unroll
        for (int jl = 0; jl < 8; jl++) dsum += s_ad[tid * 8 + jl];
        atomicAdd(&g_deg[bN + i0 + tid], dsum);
    }
}

// ---------------------------------------------------------------------------
// K6: out *= inv_i * inv_j  with inline rsqrt
// ---------------------------------------------------------------------------
__global__ void k_norm(float* __restrict__ out) {
    int idx = blockIdx.x * 256 + threadIdx.x;      // one float4 each
    int j4  = (idx & 127) * 4;                     // 128 quads per row
    int bi  = idx >> 7;                            // flat b*N+i, 0..1023
    float  inv_i = rsqrtf(fmaxf(g_deg[bi], 1e-6f));
    float4 dj    = *(const float4*)&g_deg[(bi & ~(N_ - 1)) + j4];
    float4 v = ((float4*)out)[idx];
    v.x *= inv_i * rsqrtf(fmaxf(dj.x, 1e-6f));
    v.y *= inv_i * rsqrtf(fmaxf(dj.y, 1e-6f));
    v.z *= inv_i * rsqrtf(fmaxf(dj.z, 1e-6f));
    v.w *= inv_i * rsqrtf(fmaxf(dj.w, 1e-6f));
    ((float4*)out)[idx] = v;
}

// ---------------------------------------------------------------------------
// launch
// ---------------------------------------------------------------------------
extern "C" void kernel_launch(void* const* d_in, const int* in_sizes, int n_in,
                              void* d_out, int out_size) {
    const float* x      = (const float*)d_in[0];
    const float* mask   = (const float*)d_in[1];
    const float* statc  = (const float*)d_in[2];
    const float* coords = (const float*)d_in[3];
    const float* W1     = (const float*)d_in[4];
    const float* b1     = (const float*)d_in[5];
    const float* W2     = (const float*)d_in[6];
    const float* b2     = (const float*)d_in[7];
    const float* W3     = (const float*)d_in[8];
    const float* b3     = (const float*)d_in[9];
    const float* W4     = (const float*)d_in[10];
    const float* b4     = (const float*)d_in[11];
    float* out = (float*)d_out;

    k_init<<<20, 256>>>(W3);
    k_reduce<<<dim3(N_ / 32, B_, 8), dim3(32, 8)>>>(x, mask);
    k_node<<<(B_ * N_) / 16, 256>>>(x, statc, W1, b1, W2, b2, W3, b3);
    k_edge<<<dim3(N_ / TJB, N_ / TIB, B_), 256>>>(W4, b4, coords, out);
    k_norm<<<(B_ * N_ * N_ / 4) / 256, 256>>>(out);
}

// round 15
// speedup vs baseline: 1.5274x; 1.1008x over previous
#include <cuda_runtime.h>
#include <cuda_bf16.h>
#include <cuda_fp16.h>

// Shapes (fixed by the problem)
#define B_  2
#define T_  512
#define N_  512
#define H_  64
#define S_  8
#define C_  8

// Edge-kernel tiling: block = 256 edges (32 i x 8 j), N=64 k, K=64 per array
#define TIB 32
#define TJB 8

// ---------------------------------------------------------------------------
// fp16 helpers
// ---------------------------------------------------------------------------
__device__ __forceinline__ unsigned pack_f16x2(float lo, float hi) {
    unsigned r;
    asm("cvt.rn.f16x2.f32 %0, %1, %2;" : "=r"(r) : "f"(hi), "f"(lo));
    return r;
}
__device__ __forceinline__ unsigned hsub_abs2(unsigned a, unsigned b) {
    unsigned d;
    asm("sub.rn.f16x2 %0, %1, %2;\n\tabs.f16x2 %0, %0;" : "=r"(d) : "r"(a), "r"(b));
    return d;
}
__device__ __forceinline__ unsigned hmul2u(unsigned a, unsigned b) {
    unsigned d;
    asm("mul.rn.f16x2 %0, %1, %2;" : "=r"(d) : "r"(a), "r"(b));
    return d;
}
__device__ __forceinline__ void mma_f16(float* c, const unsigned* a, unsigned b0, unsigned b1) {
    asm("mma.sync.aligned.m16n8k16.row.col.f32.f16.f16.f32 "
        "{%0,%1,%2,%3}, {%4,%5,%6,%7}, {%8,%9}, {%0,%1,%2,%3};"
        : "+f"(c[0]), "+f"(c[1]), "+f"(c[2]), "+f"(c[3])
        : "r"(a[0]), "r"(a[1]), "r"(a[2]), "r"(a[3]), "r"(b0), "r"(b1));
}

// ---------------------------------------------------------------------------
// Device scratch (no allocations allowed)
// ---------------------------------------------------------------------------
__device__ float g_repr[B_ * N_ * H_];   // node_repr
__device__ float g_Ai  [B_ * N_ * H_];   // repr @ W3[0:64]   + b3
__device__ float g_Bj  [B_ * N_ * H_];   // repr @ W3[64:128]
__device__ float g_deg [B_ * N_];        // degree accumulators
// per-node reduction stats
__device__ float g_s_sum[B_ * N_];
__device__ float g_s_sq [B_ * N_];
__device__ float g_s_cnt[B_ * N_];
__device__ float g_s_ms [B_ * N_];
__device__ int   g_s_last[B_ * N_];
// W3c/W3d as f16x2 B-fragments, interleaved for one LDS.128 per (ks,nt):
// [ks][nt][lane][4 words: bC0 bC1 bD0 bD1]
__device__ unsigned g_Wf[4 * 8 * 32 * 4];    // 16KB

// ---------------------------------------------------------------------------
// K0: init — zero accumulators (blocks 0..3) + fragment prep (blocks 4..19).
// m16n8k16.row.col B-frag: b0 = {k=2t,2t+1 | n=g}, b1 = {k=2t+8,2t+9 | n=g}.
// ---------------------------------------------------------------------------
__global__ void k_init(const float* __restrict__ W3) {
    if (blockIdx.x < 4) {
        int t = blockIdx.x * 256 + threadIdx.x;    // 0..1023
        g_deg[t] = 0.0f;
        g_s_sum[t] = 0.0f; g_s_sq[t] = 0.0f;
        g_s_cnt[t] = 0.0f; g_s_ms[t] = 0.0f;
        g_s_last[t] = 0;
    } else {
        int f = (blockIdx.x - 4) * 256 + threadIdx.x;  // 0..4095
        int w    = f & 3;            // 0=bC0 1=bC1 2=bD0 3=bD1
        int lane = (f >> 2) & 31;
        int nt   = (f >> 7) & 7;
        int ks   = (f >> 10) & 3;
        int t = lane & 3, g = lane >> 2;
        int arr = w >> 1;            // 0 = abs-part (W3 rows 128+), 1 = prod (192+)
        int k   = ks * 16 + 2 * t + (w & 1) * 8;   // within [0,64)
        int n   = nt * 8 + g;
        int rb  = 128 + arr * 64;
        g_Wf[f] = pack_f16x2(W3[(rb + k) * 64 + n], W3[(rb + k + 1) * 64 + n]);
    }
}

// ---------------------------------------------------------------------------
// K1a: chip-wide T-chunked reduction. grid (N/32, B, 8), block (32, 8).
// ---------------------------------------------------------------------------
__global__ void k_reduce(const float* __restrict__ x,
                         const float* __restrict__ mask) {
    const int tx = threadIdx.x, ty = threadIdx.y;
    const int b  = blockIdx.y;
    const int n  = blockIdx.x * 32 + tx;
    const int t0 = blockIdx.z * 64;

    __shared__ float s_sum[8][33], s_sq[8][33], s_cnt[8][33], s_ms[8][33];
    __shared__ int   s_last[8][33];

    const float* xb = x    + (size_t)b * T_ * N_;
    const float* mb = mask + (size_t)b * T_ * N_;

    float sum = 0.f, sq = 0.f, cnt = 0.f, ms = 0.f;
    int   lastt = -1;
    #pragma unroll
    for (int it = 0; it < 8; it++) {
        int t = t0 + ty + it * 8;
        float xv = xb[t * N_ + n];
        float mv = mb[t * N_ + n];
        float ob = 1.0f - mv;
        sum += xv * ob;
        sq  += xv * xv * ob;
        cnt += ob;
        ms  += mv;
        if (ob > 0.5f) lastt = t;
    }
    s_sum[ty][tx] = sum; s_sq[ty][tx] = sq; s_cnt[ty][tx] = cnt;
    s_ms[ty][tx] = ms;   s_last[ty][tx] = lastt;
    __syncthreads();

    if (ty == 0) {
        for (int r = 1; r < 8; r++) {
            sum += s_sum[r][tx]; sq += s_sq[r][tx]; cnt += s_cnt[r][tx];
            ms  += s_ms[r][tx];
            lastt = max(lastt, s_last[r][tx]);
        }
        int idx = b * N_ + n;
        atomicAdd(&g_s_sum[idx], sum);
        atomicAdd(&g_s_sq [idx], sq);
        atomicAdd(&g_s_cnt[idx], cnt);
        atomicAdd(&g_s_ms [idx], ms);
        if (lastt >= 0) atomicMax(&g_s_last[idx], lastt);
    }
}

// ---------------------------------------------------------------------------
// K1b (fused): finalize stats -> feats -> layer1 -> layer2 -> Ai/Bj.
// grid 64 blocks x 16 nodes; block 256 = 16 nodes x 16 k-lanes (4 k each).
// ---------------------------------------------------------------------------
__global__ __launch_bounds__(256)
void k_node(const float* __restrict__ x,
            const float* __restrict__ statc,
            const float* __restrict__ W1,
            const float* __restrict__ b1,
            const float* __restrict__ W2,
            const float* __restrict__ b2,
            const float* __restrict__ W3,
            const float* __restrict__ b3) {
    __shared__ float s_w[128 * 64];      // 32KB union: [W1(768) W2(4096)] then W3ab(8192)
    __shared__ float s_f[16][13];        // feats
    __shared__ float s_h[16][65];        // hidden
    __shared__ float s_r[16][65];        // repr

    const int tid = threadIdx.x;
    const int ng0 = blockIdx.x * 16;     // flat (b*N + n) base; never straddles batch

    for (int idx = tid; idx < 768; idx += 256)  s_w[idx] = W1[idx];
    for (int idx = tid; idx < 4096; idx += 256) s_w[768 + idx] = W2[idx];

    if (tid < 16) {
        int idx = ng0 + tid;
        int b = idx >> 9, n = idx & (N_ - 1);
        float sum = g_s_sum[idx], sq = g_s_sq[idx];
        float cnt = g_s_cnt[idx], ms = g_s_ms[idx];
        int lastt = g_s_last[idx];
        float count = fmaxf(cnt, 1.0f);
        float mean  = sum / count;
        float var   = (sq - 2.0f * mean * sum + mean * mean * cnt) / count;
        float stdv  = sqrtf(fmaxf(var, 0.0f) + 1e-6f);
        float last  = x[((size_t)b * T_ + lastt) * N_ + n];
        s_f[tid][0] = mean; s_f[tid][1] = stdv; s_f[tid][2] = last;
        s_f[tid][3] = ms * (1.0f / (float)T_);
    }
    if (tid < 128) {
        int nl = tid >> 3, s = tid & 7;
        s_f[nl][4 + s] = statc[((ng0 + nl) & (N_ - 1)) * S_ + s];
    }
    __syncthreads();

    const int nl = tid >> 4;             // node-in-block
    const int kl = tid & 15;             // k-lane

    #pragma unroll
    for (int kk = 0; kk < 4; kk++) {
        int k = kl + 16 * kk;
        float a = b1[k];
        #pragma unroll
        for (int f = 0; f < 12; f++) a += s_f[nl][f] * s_w[f * 64 + k];
        s_h[nl][k] = fmaxf(a, 0.0f);
    }
    __syncthreads();

    #pragma unroll
    for (int kk = 0; kk < 4; kk++) {
        int k = kl + 16 * kk;
        float a = b2[k];
        #pragma unroll
        for (int h = 0; h < 64; h++) a += s_h[nl][h] * s_w[768 + h * 64 + k];
        float r = fmaxf(a, 0.0f);
        s_r[nl][k] = r;
        g_repr[(ng0 + nl) * H_ + k] = r;
    }
    __syncthreads();

    for (int idx = tid; idx < 8192; idx += 256) s_w[idx] = W3[idx];
    __syncthreads();

    #pragma unroll
    for (int kk = 0; kk < 4; kk++) {
        int k = kl + 16 * kk;
        float a = b3[k], bj = 0.0f;
        #pragma unroll
        for (int h = 0; h < 64; h++) {
            float r = s_r[nl][h];
            a  += r * s_w[h * 64 + k];
            bj += r * s_w[(64 + h) * 64 + k];
        }
        g_Ai[(ng0 + nl) * H_ + k] = a;
        g_Bj[(ng0 + nl) * H_ + k] = bj;
    }
}

// ---------------------------------------------------------------------------
// K4: edge MLP via fp16 mma.sync m16n8k16 (fp32 accum); prior inline.
// Block tile: M=256 edges (32i x 8j), per-array K=64 -> 4 k16 steps.
// 8 warps = 8 m-groups (32 edges), each covers full N=64.
// hi/hj pre-packed to f16x2 words in the PROLOGUE (s_hi2/s_hj2), so the
// mainloop A-build is pure f16x2 ALU (sub+abs / mul) with LDS.32 broadcasts —
// no cvt, no re-reads.  aD+aP both live (16 regs) feed 4 mmas per LDS.128
// B-fragment.  __launch_bounds__(256,2) pins 2 blocks/SM.
// grid (N/TJB, N/TIB, B), block 256.
// ---------------------------------------------------------------------------
__global__ __launch_bounds__(256, 2)
void k_edge(const float* __restrict__ W4,
            const float* __restrict__ b4p,
            const float* __restrict__ coords,
            float* __restrict__ out) {
    __shared__ unsigned s_hi2[32][36];           // f16x2 words, pad 36 -> conflict-free
    __shared__ unsigned s_hj2[8][36];
    __shared__ unsigned s_Wf[4][8][32][4];       // 16KB frag buffer, reused as Ai/Bj
    __shared__ float s_ed[256];                  // per-edge pre-b4 sums
    __shared__ float s_ad[256];
    __shared__ float s_W4[64];
    __shared__ float s_ci[32][8];
    __shared__ float s_cj[8][8];

    const int tid = threadIdx.x;
    const int b   = blockIdx.z;
    const int i0  = blockIdx.y * TIB;
    const int j0  = blockIdx.x * TJB;
    const int bN  = b * N_;

    const float* reprB = g_repr + (size_t)bN * H_;

    // prologue: pack hi/hj rows to f16x2 (word w = k-pair {2w, 2w+1})
    for (int idx = tid; idx < 32 * 32; idx += 256) {
        int il = idx >> 5, w = idx & 31;
        float2 v = *(const float2*)&reprB[(i0 + il) * H_ + 2 * w];
        s_hi2[il][w] = pack_f16x2(v.x, v.y);
    }
    if (tid < 256) {                             // 8*32 = 256 words
        int jl = tid >> 5, w = tid & 31;
        float2 v = *(const float2*)&reprB[(j0 + jl) * H_ + 2 * w];
        s_hj2[jl][w] = pack_f16x2(v.x, v.y);
    }
    {
        const uint4* src = (const uint4*)g_Wf;
        uint4* dst = (uint4*)&s_Wf[0][0][0][0];
        for (int idx = tid; idx < 1024; idx += 256) dst[idx] = src[idx];
    }
    if (tid < 64) s_W4[tid] = W4[tid];
    s_ci[tid >> 3][tid & 7] = coords[(i0 + (tid >> 3)) * C_ + (tid & 7)];
    if (tid < 64) s_cj[tid >> 3][tid & 7] = coords[(j0 + (tid >> 3)) * C_ + (tid & 7)];
    __syncthreads();

    const int wid = tid >> 5, lane = tid & 31;   // warp = m-group of 32 edges
    const int g = lane >> 2, t = lane & 3;       // g = jl, t = k-quad

    float acc[2][8][4];
    #pragma unroll
    for (int mt = 0; mt < 2; mt++)
        #pragma unroll
        for (int nt = 0; nt < 8; nt++)
            #pragma unroll
            for (int q = 0; q < 4; q++) acc[mt][nt][q] = 0.0f;

    #pragma unroll
    for (int ks = 0; ks < 4; ks++) {             // k16 step over H=64
        const int wb = ks * 8 + t;               // word index of k-pair
        const unsigned hjA = s_hj2[g][wb], hjB = s_hj2[g][wb + 4];
        unsigned aD[2][4], aP[2][4];
        #pragma unroll
        for (int mt = 0; mt < 2; mt++) {
            const int il0 = wid * 4 + mt * 2;
            const unsigned h0  = s_hi2[il0][wb],     h0b = s_hi2[il0][wb + 4];
            const unsigned h1  = s_hi2[il0 + 1][wb], h1b = s_hi2[il0 + 1][wb + 4];
            aD[mt][0] = hsub_abs2(h0,  hjA);
            aD[mt][1] = hsub_abs2(h1,  hjA);
            aD[mt][2] = hsub_abs2(h0b, hjB);
            aD[mt][3] = hsub_abs2(h1b, hjB);
            aP[mt][0] = hmul2u(h0,  hjA);
            aP[mt][1] = hmul2u(h1,  hjA);
            aP[mt][2] = hmul2u(h0b, hjB);
            aP[mt][3] = hmul2u(h1b, hjB);
        }
        #pragma unroll
        for (int nt = 0; nt < 8; nt++) {
            uint4 fr = *(const uint4*)&s_Wf[ks][nt][lane][0];
            mma_f16(acc[0][nt], aD[0], fr.x, fr.y);
            mma_f16(acc[1][nt], aD[1], fr.x, fr.y);
            mma_f16(acc[0][nt], aP[0], fr.z, fr.w);
            mma_f16(acc[1][nt], aP[1], fr.z, fr.w);
        }
    }

    // restage Ai/Bj into smem reused from the fragment buffer (16KB >= 10KB)
    __syncthreads();
    float* s_Ais = (float*)&s_Wf[0][0][0][0];    // [32][64]
    float* s_Bjs = s_Ais + 32 * 64;              // [8][64]
    {
        const float4* srcA = (const float4*)(g_Ai + (size_t)(bN + i0) * H_);
        float4* dstA = (float4*)s_Ais;
        for (int idx = tid; idx < 512; idx += 256) dstA[idx] = srcA[idx];
        const float4* srcB = (const float4*)(g_Bj + (size_t)(bN + j0) * H_);
        float4* dstB = (float4*)s_Bjs;
        if (tid < 128) dstB[tid] = srcB[tid];
    }
    __syncthreads();

    // epilogue: e_k = relu(acc + Ai + Bj); dot with W4, quad-reduce.
    #pragma unroll
    for (int mt = 0; mt < 2; mt++) {
        #pragma unroll
        for (int half = 0; half < 2; half++) {
            const int il = wid * 4 + mt * 2 + half;
            const int jl = g;
            float s = 0.0f;
            #pragma unroll
            for (int nt = 0; nt < 8; nt++) {
                const int k0 = nt * 8 + 2 * t;
                float ab0 = s_Ais[il * 64 + k0]     + s_Bjs[jl * 64 + k0];
                float ab1 = s_Ais[il * 64 + k0 + 1] + s_Bjs[jl * 64 + k0 + 1];
                float v0 = fmaxf(acc[mt][nt][half * 2]     + ab0, 0.0f);
                float v1 = fmaxf(acc[mt][nt][half * 2 + 1] + ab1, 0.0f);
                s += v0 * s_W4[k0] + v1 * s_W4[k0 + 1];
            }
            s += __shfl_xor_sync(0xffffffffu, s, 1);
            s += __shfl_xor_sync(0xffffffffu, s, 2);
            if (t == 0) s_ed[wid * 32 + mt * 16 + half * 8 + g] = s;
        }
    }
    __syncthreads();

    {
        const float b4v = b4p[0];
        int e  = tid;                            // 0..255
        int il = e >> 3, jl = e & 7;
        int i  = i0 + il, j = j0 + jl;
        float edge = fmaxf(s_ed[e] + b4v, 0.0f);
        float d2 = 0.0f;
        #pragma unroll
        for (int c = 0; c < C_; c++) {
            float d = s_ci[il][c] - s_cj[jl][c];
            d2 += d * d;
        }
        float pr = (i == j) ? 0.0f : 1.0f / (1.0f + sqrtf(d2));
        float ad = edge * pr + ((i == j) ? 1.0f : 0.0f);
        out[((size_t)(bN + i)) * N_ + j] = ad;   // adapt (pre-normalization)
        s_ad[e] = ad;
    }
    __syncthreads();

    if (tid < 32) {
        float dsum = 0.0f;
        #pragma unroll
        for (int jl = 0; jl < 8; jl++) dsum += s_ad[tid * 8 + jl];
        atomicAdd(&g_deg[bN + i0 + tid], dsum);
    }
}

// ---------------------------------------------------------------------------
// K6: out *= inv_i * inv_j  with inline rsqrt
// ---------------------------------------------------------------------------
__global__ void k_norm(float* __restrict__ out) {
    int idx = blockIdx.x * 256 + threadIdx.x;      // one float4 each
    int j4  = (idx & 127) * 4;                     // 128 quads per row
    int bi  = idx >> 7;                            // flat b*N+i, 0..1023
    float  inv_i = rsqrtf(fmaxf(g_deg[bi], 1e-6f));
    float4 dj    = *(const float4*)&g_deg[(bi & ~(N_ - 1)) + j4];
    float4 v = ((float4*)out)[idx];
    v.x *= inv_i * rsqrtf(fmaxf(dj.x, 1e-6f));
    v.y *= inv_i * rsqrtf(fmaxf(dj.y, 1e-6f));
    v.z *= inv_i * rsqrtf(fmaxf(dj.z, 1e-6f));
    v.w *= inv_i * rsqrtf(fmaxf(dj.w, 1e-6f));
    ((float4*)out)[idx] = v;
}

// ---------------------------------------------------------------------------
// launch
// ---------------------------------------------------------------------------
extern "C" void kernel_launch(void* const* d_in, const int* in_sizes, int n_in,
                              void* d_out, int out_size) {
    const float* x      = (const float*)d_in[0];
    const float* mask   = (const float*)d_in[1];
    const float* statc  = (const float*)d_in[2];
    const float* coords = (const float*)d_in[3];
    const float* W1     = (const float*)d_in[4];
    const float* b1     = (const float*)d_in[5];
    const float* W2     = (const float*)d_in[6];
    const float* b2     = (const float*)d_in[7];
    const float* W3     = (const float*)d_in[8];
    const float* b3     = (const float*)d_in[9];
    const float* W4     = (const float*)d_in[10];
    const float* b4     = (const float*)d_in[11];
    float* out = (float*)d_out;

    k_init<<<20, 256>>>(W3);
    k_reduce<<<dim3(N_ / 32, B_, 8), dim3(32, 8)>>>(x, mask);
    k_node<<<(B_ * N_) / 16, 256>>>(x, statc, W1, b1, W2, b2, W3, b3);
    k_edge<<<dim3(N_ / TJB, N_ / TIB, B_), 256>>>(W4, b4, coords, out);
    k_norm<<<(B_ * N_ * N_ / 4) / 256, 256>>>(out);
}

// round 16
// speedup vs baseline: 1.5584x; 1.0203x over previous
#include <cuda_runtime.h>
#include <cuda_bf16.h>
#include <cuda_fp16.h>

// Shapes (fixed by the problem)
#define B_  2
#define T_  512
#define N_  512
#define H_  64
#define S_  8
#define C_  8

// Edge-kernel tiling: block = 256 edges (32 i x 8 j), N=64 k, K=64 per array
#define TIB 32
#define TJB 8

// ---------------------------------------------------------------------------
// fp16 helpers
// ---------------------------------------------------------------------------
__device__ __forceinline__ unsigned pack_f16x2(float lo, float hi) {
    unsigned r;
    asm("cvt.rn.f16x2.f32 %0, %1, %2;" : "=r"(r) : "f"(hi), "f"(lo));
    return r;
}
__device__ __forceinline__ unsigned hsub_abs2(unsigned a, unsigned b) {
    unsigned d;
    asm("sub.rn.f16x2 %0, %1, %2;\n\tabs.f16x2 %0, %0;" : "=r"(d) : "r"(a), "r"(b));
    return d;
}
__device__ __forceinline__ unsigned hmul2u(unsigned a, unsigned b) {
    unsigned d;
    asm("mul.rn.f16x2 %0, %1, %2;" : "=r"(d) : "r"(a), "r"(b));
    return d;
}
__device__ __forceinline__ void mma_f16(float* c, const unsigned* a, unsigned b0, unsigned b1) {
    asm("mma.sync.aligned.m16n8k16.row.col.f32.f16.f16.f32 "
        "{%0,%1,%2,%3}, {%4,%5,%6,%7}, {%8,%9}, {%0,%1,%2,%3};"
        : "+f"(c[0]), "+f"(c[1]), "+f"(c[2]), "+f"(c[3])
        : "r"(a[0]), "r"(a[1]), "r"(a[2]), "r"(a[3]), "r"(b0), "r"(b1));
}

// ---------------------------------------------------------------------------
// Device scratch (no allocations allowed)
// ---------------------------------------------------------------------------
__device__ float g_repr[B_ * N_ * H_];   // node_repr
__device__ float g_Ai  [B_ * N_ * H_];   // repr @ W3[0:64]   + b3
__device__ float g_Bj  [B_ * N_ * H_];   // repr @ W3[64:128]
__device__ float g_deg [B_ * N_];        // degree accumulators
// per-node reduction stats
__device__ float g_s_sum[B_ * N_];
__device__ float g_s_sq [B_ * N_];
__device__ float g_s_cnt[B_ * N_];
__device__ float g_s_ms [B_ * N_];
__device__ int   g_s_last[B_ * N_];
// W3c/W3d as f16x2 B-fragments, interleaved for one LDS.128 per (ks,nt):
// [ks][nt][lane][4 words: bC0 bC1 bD0 bD1]
__device__ unsigned g_Wf[4 * 8 * 32 * 4];    // 16KB

// ---------------------------------------------------------------------------
// K0: init — zero accumulators (blocks 0..3) + fragment prep (blocks 4..19).
// m16n8k16.row.col B-frag: b0 = {k=2t,2t+1 | n=g}, b1 = {k=2t+8,2t+9 | n=g}.
// ---------------------------------------------------------------------------
__global__ void k_init(const float* __restrict__ W3) {
    if (blockIdx.x < 4) {
        int t = blockIdx.x * 256 + threadIdx.x;    // 0..1023
        g_deg[t] = 0.0f;
        g_s_sum[t] = 0.0f; g_s_sq[t] = 0.0f;
        g_s_cnt[t] = 0.0f; g_s_ms[t] = 0.0f;
        g_s_last[t] = 0;
    } else {
        int f = (blockIdx.x - 4) * 256 + threadIdx.x;  // 0..4095
        int w    = f & 3;            // 0=bC0 1=bC1 2=bD0 3=bD1
        int lane = (f >> 2) & 31;
        int nt   = (f >> 7) & 7;
        int ks   = (f >> 10) & 3;
        int t = lane & 3, g = lane >> 2;
        int arr = w >> 1;            // 0 = abs-part (W3 rows 128+), 1 = prod (192+)
        int k   = ks * 16 + 2 * t + (w & 1) * 8;   // within [0,64)
        int n   = nt * 8 + g;
        int rb  = 128 + arr * 64;
        g_Wf[f] = pack_f16x2(W3[(rb + k) * 64 + n], W3[(rb + k + 1) * 64 + n]);
    }
}

// ---------------------------------------------------------------------------
// K1a: chip-wide T-chunked reduction. grid (N/32, B, 8), block (32, 8).
// ---------------------------------------------------------------------------
__global__ void k_reduce(const float* __restrict__ x,
                         const float* __restrict__ mask) {
    const int tx = threadIdx.x, ty = threadIdx.y;
    const int b  = blockIdx.y;
    const int n  = blockIdx.x * 32 + tx;
    const int t0 = blockIdx.z * 64;

    __shared__ float s_sum[8][33], s_sq[8][33], s_cnt[8][33], s_ms[8][33];
    __shared__ int   s_last[8][33];

    const float* xb = x    + (size_t)b * T_ * N_;
    const float* mb = mask + (size_t)b * T_ * N_;

    float sum = 0.f, sq = 0.f, cnt = 0.f, ms = 0.f;
    int   lastt = -1;
    #pragma unroll
    for (int it = 0; it < 8; it++) {
        int t = t0 + ty + it * 8;
        float xv = xb[t * N_ + n];
        float mv = mb[t * N_ + n];
        float ob = 1.0f - mv;
        sum += xv * ob;
        sq  += xv * xv * ob;
        cnt += ob;
        ms  += mv;
        if (ob > 0.5f) lastt = t;
    }
    s_sum[ty][tx] = sum; s_sq[ty][tx] = sq; s_cnt[ty][tx] = cnt;
    s_ms[ty][tx] = ms;   s_last[ty][tx] = lastt;
    __syncthreads();

    if (ty == 0) {
        for (int r = 1; r < 8; r++) {
            sum += s_sum[r][tx]; sq += s_sq[r][tx]; cnt += s_cnt[r][tx];
            ms  += s_ms[r][tx];
            lastt = max(lastt, s_last[r][tx]);
        }
        int idx = b * N_ + n;
        atomicAdd(&g_s_sum[idx], sum);
        atomicAdd(&g_s_sq [idx], sq);
        atomicAdd(&g_s_cnt[idx], cnt);
        atomicAdd(&g_s_ms [idx], ms);
        if (lastt >= 0) atomicMax(&g_s_last[idx], lastt);
    }
}

// ---------------------------------------------------------------------------
// K1b (fused): finalize stats -> feats -> layer1 -> layer2 -> Ai/Bj.
// grid 64 blocks x 16 nodes; block 256 = 16 nodes x 16 k-lanes (4 k each).
// ---------------------------------------------------------------------------
__global__ __launch_bounds__(256)
void k_node(const float* __restrict__ x,
            const float* __restrict__ statc,
            const float* __restrict__ W1,
            const float* __restrict__ b1,
            const float* __restrict__ W2,
            const float* __restrict__ b2,
            const float* __restrict__ W3,
            const float* __restrict__ b3) {
    __shared__ float s_w[128 * 64];      // 32KB union: [W1(768) W2(4096)] then W3ab(8192)
    __shared__ float s_f[16][13];        // feats
    __shared__ float s_h[16][65];        // hidden
    __shared__ float s_r[16][65];        // repr

    const int tid = threadIdx.x;
    const int ng0 = blockIdx.x * 16;     // flat (b*N + n) base; never straddles batch

    for (int idx = tid; idx < 768; idx += 256)  s_w[idx] = W1[idx];
    for (int idx = tid; idx < 4096; idx += 256) s_w[768 + idx] = W2[idx];

    if (tid < 16) {
        int idx = ng0 + tid;
        int b = idx >> 9, n = idx & (N_ - 1);
        float sum = g_s_sum[idx], sq = g_s_sq[idx];
        float cnt = g_s_cnt[idx], ms = g_s_ms[idx];
        int lastt = g_s_last[idx];
        float count = fmaxf(cnt, 1.0f);
        float mean  = sum / count;
        float var   = (sq - 2.0f * mean * sum + mean * mean * cnt) / count;
        float stdv  = sqrtf(fmaxf(var, 0.0f) + 1e-6f);
        float last  = x[((size_t)b * T_ + lastt) * N_ + n];
        s_f[tid][0] = mean; s_f[tid][1] = stdv; s_f[tid][2] = last;
        s_f[tid][3] = ms * (1.0f / (float)T_);
    }
    if (tid < 128) {
        int nl = tid >> 3, s = tid & 7;
        s_f[nl][4 + s] = statc[((ng0 + nl) & (N_ - 1)) * S_ + s];
    }
    __syncthreads();

    const int nl = tid >> 4;             // node-in-block
    const int kl = tid & 15;             // k-lane

    #pragma unroll
    for (int kk = 0; kk < 4; kk++) {
        int k = kl + 16 * kk;
        float a = b1[k];
        #pragma unroll
        for (int f = 0; f < 12; f++) a += s_f[nl][f] * s_w[f * 64 + k];
        s_h[nl][k] = fmaxf(a, 0.0f);
    }
    __syncthreads();

    #pragma unroll
    for (int kk = 0; kk < 4; kk++) {
        int k = kl + 16 * kk;
        float a = b2[k];
        #pragma unroll
        for (int h = 0; h < 64; h++) a += s_h[nl][h] * s_w[768 + h * 64 + k];
        float r = fmaxf(a, 0.0f);
        s_r[nl][k] = r;
        g_repr[(ng0 + nl) * H_ + k] = r;
    }
    __syncthreads();

    for (int idx = tid; idx < 8192; idx += 256) s_w[idx] = W3[idx];
    __syncthreads();

    #pragma unroll
    for (int kk = 0; kk < 4; kk++) {
        int k = kl + 16 * kk;
        float a = b3[k], bj = 0.0f;
        #pragma unroll
        for (int h = 0; h < 64; h++) {
            float r = s_r[nl][h];
            a  += r * s_w[h * 64 + k];
            bj += r * s_w[(64 + h) * 64 + k];
        }
        g_Ai[(ng0 + nl) * H_ + k] = a;
        g_Bj[(ng0 + nl) * H_ + k] = bj;
    }
}

// ---------------------------------------------------------------------------
// K4: edge MLP via fp16 mma.sync m16n8k16 (fp32 accum); prior inline.
// Block tile: M=256 edges (32i x 8j), per-array K=64 -> 4 k16 steps.
// NOW 512 threads = 16 warps = 8 m-groups x 2 n-halves: each warp covers
// 32 edges x 32 k -> acc = 32 regs/thread (was 64).  __launch_bounds__(512,2)
// pins <=64 regs -> 32 warps/SM (2x occupancy vs R15) to hide LDS/mma latency
// that had every pipe idling at ~30%.  A-build duplicated across n-halves but
// it is cheap f16x2 ALU on pre-packed smem words.
// grid (N/TJB, N/TIB, B), block 512.
// ---------------------------------------------------------------------------
__global__ __launch_bounds__(512, 2)
void k_edge(const float* __restrict__ W4,
            const float* __restrict__ b4p,
            const float* __restrict__ coords,
            float* __restrict__ out) {
    __shared__ unsigned s_hi2[32][36];           // f16x2 words, pad 36 -> conflict-free
    __shared__ unsigned s_hj2[8][36];
    __shared__ unsigned s_Wf[4][8][32][4];       // 16KB frag buffer, reused as Ai/Bj
    __shared__ float s_part[2][256];             // per-n-half partial edge sums
    __shared__ float s_ad[256];
    __shared__ float s_W4[64];
    __shared__ float s_ci[32][8];
    __shared__ float s_cj[8][8];

    const int tid = threadIdx.x;
    const int b   = blockIdx.z;
    const int i0  = blockIdx.y * TIB;
    const int j0  = blockIdx.x * TJB;
    const int bN  = b * N_;

    const float* reprB = g_repr + (size_t)bN * H_;

    // prologue: pack hi/hj rows to f16x2 (word w = k-pair {2w, 2w+1})
    for (int idx = tid; idx < 32 * 32; idx += 512) {
        int il = idx >> 5, w = idx & 31;
        float2 v = *(const float2*)&reprB[(i0 + il) * H_ + 2 * w];
        s_hi2[il][w] = pack_f16x2(v.x, v.y);
    }
    if (tid < 256) {                             // 8*32 = 256 words
        int jl = tid >> 5, w = tid & 31;
        float2 v = *(const float2*)&reprB[(j0 + jl) * H_ + 2 * w];
        s_hj2[jl][w] = pack_f16x2(v.x, v.y);
    }
    {
        const uint4* src = (const uint4*)g_Wf;
        uint4* dst = (uint4*)&s_Wf[0][0][0][0];
        for (int idx = tid; idx < 1024; idx += 512) dst[idx] = src[idx];
    }
    if (tid < 64) s_W4[tid] = W4[tid];
    if (tid < 256) s_ci[tid >> 3][tid & 7] = coords[(i0 + (tid >> 3)) * C_ + (tid & 7)];
    if (tid < 64) s_cj[tid >> 3][tid & 7] = coords[(j0 + (tid >> 3)) * C_ + (tid & 7)];
    __syncthreads();

    const int wid = tid >> 5, lane = tid & 31;
    const int mg = wid & 7;                      // m-group: 32 edges
    const int nh = wid >> 3;                     // n-half: 32 k
    const int g = lane >> 2, t = lane & 3;       // g = jl, t = k-quad

    float acc[2][4][4];
    #pragma unroll
    for (int mt = 0; mt < 2; mt++)
        #pragma unroll
        for (int nt = 0; nt < 4; nt++)
            #pragma unroll
            for (int q = 0; q < 4; q++) acc[mt][nt][q] = 0.0f;

    #pragma unroll
    for (int ks = 0; ks < 4; ks++) {             // k16 step over H=64
        const int wb = ks * 8 + t;               // word index of k-pair
        const unsigned hjA = s_hj2[g][wb], hjB = s_hj2[g][wb + 4];
        unsigned aD[2][4], aP[2][4];
        #pragma unroll
        for (int mt = 0; mt < 2; mt++) {
            const int il0 = mg * 4 + mt * 2;
            const unsigned h0  = s_hi2[il0][wb],     h0b = s_hi2[il0][wb + 4];
            const unsigned h1  = s_hi2[il0 + 1][wb], h1b = s_hi2[il0 + 1][wb + 4];
            aD[mt][0] = hsub_abs2(h0,  hjA);
            aD[mt][1] = hsub_abs2(h1,  hjA);
            aD[mt][2] = hsub_abs2(h0b, hjB);
            aD[mt][3] = hsub_abs2(h1b, hjB);
            aP[mt][0] = hmul2u(h0,  hjA);
            aP[mt][1] = hmul2u(h1,  hjA);
            aP[mt][2] = hmul2u(h0b, hjB);
            aP[mt][3] = hmul2u(h1b, hjB);
        }
        #pragma unroll
        for (int nt = 0; nt < 4; nt++) {
            uint4 fr = *(const uint4*)&s_Wf[ks][nh * 4 + nt][lane][0];
            mma_f16(acc[0][nt], aD[0], fr.x, fr.y);
            mma_f16(acc[1][nt], aD[1], fr.x, fr.y);
            mma_f16(acc[0][nt], aP[0], fr.z, fr.w);
            mma_f16(acc[1][nt], aP[1], fr.z, fr.w);
        }
    }

    // restage Ai/Bj into smem reused from the fragment buffer (16KB >= 10KB)
    __syncthreads();
    float* s_Ais = (float*)&s_Wf[0][0][0][0];    // [32][64]
    float* s_Bjs = s_Ais + 32 * 64;              // [8][64]
    {
        const float4* srcA = (const float4*)(g_Ai + (size_t)(bN + i0) * H_);
        float4* dstA = (float4*)s_Ais;
        dstA[tid] = srcA[tid];                   // 512 float4 = exactly 1/thread
        const float4* srcB = (const float4*)(g_Bj + (size_t)(bN + j0) * H_);
        float4* dstB = (float4*)s_Bjs;
        if (tid < 128) dstB[tid] = srcB[tid];
    }
    __syncthreads();

    // epilogue: e_k = relu(acc + Ai + Bj); dot with W4 over this warp's 32 k,
    // quad-reduce, then combine the two n-halves.
    #pragma unroll
    for (int mt = 0; mt < 2; mt++) {
        #pragma unroll
        for (int half = 0; half < 2; half++) {
            const int il = mg * 4 + mt * 2 + half;
            const int jl = g;
            float s = 0.0f;
            #pragma unroll
            for (int nt = 0; nt < 4; nt++) {
                const int k0 = (nh * 4 + nt) * 8 + 2 * t;
                float ab0 = s_Ais[il * 64 + k0]     + s_Bjs[jl * 64 + k0];
                float ab1 = s_Ais[il * 64 + k0 + 1] + s_Bjs[jl * 64 + k0 + 1];
                float v0 = fmaxf(acc[mt][nt][half * 2]     + ab0, 0.0f);
                float v1 = fmaxf(acc[mt][nt][half * 2 + 1] + ab1, 0.0f);
                s += v0 * s_W4[k0] + v1 * s_W4[k0 + 1];
            }
            s += __shfl_xor_sync(0xffffffffu, s, 1);
            s += __shfl_xor_sync(0xffffffffu, s, 2);
            if (t == 0) s_part[nh][mg * 32 + mt * 16 + half * 8 + g] = s;
        }
    }
    __syncthreads();

    if (tid < 256) {
        const float b4v = b4p[0];
        int e  = tid;                            // 0..255
        int il = e >> 3, jl = e & 7;
        int i  = i0 + il, j = j0 + jl;
        float edge = fmaxf(s_part[0][e] + s_part[1][e] + b4v, 0.0f);
        float d2 = 0.0f;
        #pragma unroll
        for (int c = 0; c < C_; c++) {
            float d = s_ci[il][c] - s_cj[jl][c];
            d2 += d * d;
        }
        float pr = (i == j) ? 0.0f : 1.0f / (1.0f + sqrtf(d2));
        float ad = edge * pr + ((i == j) ? 1.0f : 0.0f);
        out[((size_t)(bN + i)) * N_ + j] = ad;   // adapt (pre-normalization)
        s_ad[e] = ad;
    }
    __syncthreads();

    if (tid < 32) {
        float dsum = 0.0f;
        #pragma unroll
        for (int jl = 0; jl < 8; jl++) dsum += s_ad[tid * 8 + jl];
        atomicAdd(&g_deg[bN + i0 + tid], dsum);
    }
}

// ---------------------------------------------------------------------------
// K6: out *= inv_i * inv_j  with inline rsqrt
// ---------------------------------------------------------------------------
__global__ void k_norm(float* __restrict__ out) {
    int idx = blockIdx.x * 256 + threadIdx.x;      // one float4 each
    int j4  = (idx & 127) * 4;                     // 128 quads per row
    int bi  = idx >> 7;                            // flat b*N+i, 0..1023
    float  inv_i = rsqrtf(fmaxf(g_deg[bi], 1e-6f));
    float4 dj    = *(const float4*)&g_deg[(bi & ~(N_ - 1)) + j4];
    float4 v = ((float4*)out)[idx];
    v.x *= inv_i * rsqrtf(fmaxf(dj.x, 1e-6f));
    v.y *= inv_i * rsqrtf(fmaxf(dj.y, 1e-6f));
    v.z *= inv_i * rsqrtf(fmaxf(dj.z, 1e-6f));
    v.w *= inv_i * rsqrtf(fmaxf(dj.w, 1e-6f));
    ((float4*)out)[idx] = v;
}

// ---------------------------------------------------------------------------
// launch
// ---------------------------------------------------------------------------
extern "C" void kernel_launch(void* const* d_in, const int* in_sizes, int n_in,
                              void* d_out, int out_size) {
    const float* x      = (const float*)d_in[0];
    const float* mask   = (const float*)d_in[1];
    const float* statc  = (const float*)d_in[2];
    const float* coords = (const float*)d_in[3];
    const float* W1     = (const float*)d_in[4];
    const float* b1     = (const float*)d_in[5];
    const float* W2     = (const float*)d_in[6];
    const float* b2     = (const float*)d_in[7];
    const float* W3     = (const float*)d_in[8];
    const float* b3     = (const float*)d_in[9];
    const float* W4     = (const float*)d_in[10];
    const float* b4     = (const float*)d_in[11];
    float* out = (float*)d_out;

    k_init<<<20, 256>>>(W3);
    k_reduce<<<dim3(N_ / 32, B_, 8), dim3(32, 8)>>>(x, mask);
    k_node<<<(B_ * N_) / 16, 256>>>(x, statc, W1, b1, W2, b2, W3, b3);
    k_edge<<<dim3(N_ / TJB, N_ / TIB, B_), 512>>>(W4, b4, coords, out);
    k_norm<<<(B_ * N_ * N_ / 4) / 256, 256>>>(out);
}